// round 14
// baseline (speedup 1.0000x reference)
#include <cuda_runtime.h>
#include <math.h>
#include <stdint.h>

// Problem constants
#define TT 512
#define NB 64
#define DD 1024
#define HH 1024
#define TH 3072   // 3*H

// Scratch for gi = x @ w_ih^T + b_ih : [T*N, 3H] fp32 = 402 MB
__device__ float g_gi[TT * NB * TH];

// ---------------------------------------------------------------------------
// Kernel 1: gi GEMM.  C[M=32768, N=3072] = A[M,1024] @ B[3072,1024]^T + bias
// (unchanged — known good, ~1.4 ms)
// ---------------------------------------------------------------------------
__global__ __launch_bounds__(256) void gi_gemm_kernel(
    const float* __restrict__ A,
    const float* __restrict__ B,
    const float* __restrict__ bias,
    float* __restrict__ C)
{
    __shared__ float As[16][132];
    __shared__ float Bs[16][132];

    const int tid = threadIdx.x;
    const int m0 = blockIdx.y * 128;
    const int n0 = blockIdx.x * 128;
    const int tx = tid & 15;
    const int ty = tid >> 4;
    const int lRow = tid >> 2;
    const int lK   = (tid & 3) * 4;

    float acc[8][8];
#pragma unroll
    for (int i = 0; i < 8; i++)
#pragma unroll
        for (int j = 0; j < 8; j++) acc[i][j] = 0.f;

    for (int k0 = 0; k0 < DD; k0 += 16) {
#pragma unroll
        for (int r = 0; r < 2; r++) {
            int mm = lRow + r * 64;
            float4 va = *(const float4*)&A[(size_t)(m0 + mm) * DD + k0 + lK];
            As[lK + 0][mm] = va.x; As[lK + 1][mm] = va.y;
            As[lK + 2][mm] = va.z; As[lK + 3][mm] = va.w;
            float4 vb = *(const float4*)&B[(size_t)(n0 + mm) * DD + k0 + lK];
            Bs[lK + 0][mm] = vb.x; Bs[lK + 1][mm] = vb.y;
            Bs[lK + 2][mm] = vb.z; Bs[lK + 3][mm] = vb.w;
        }
        __syncthreads();
#pragma unroll
        for (int k = 0; k < 16; k++) {
            float a[8], b[8];
            *(float4*)&a[0] = *(float4*)&As[k][ty * 4];
            *(float4*)&a[4] = *(float4*)&As[k][64 + ty * 4];
            *(float4*)&b[0] = *(float4*)&Bs[k][tx * 4];
            *(float4*)&b[4] = *(float4*)&Bs[k][64 + tx * 4];
#pragma unroll
            for (int i = 0; i < 8; i++)
#pragma unroll
                for (int j = 0; j < 8; j++)
                    acc[i][j] += a[i] * b[j];
        }
        __syncthreads();
    }

#pragma unroll
    for (int i = 0; i < 8; i++) {
        int m = m0 + ((i < 4) ? (ty * 4 + i) : (64 + ty * 4 + i - 4));
#pragma unroll
        for (int j = 0; j < 8; j++) {
            int n = n0 + ((j < 4) ? (tx * 4 + j) : (64 + tx * 4 + j - 4));
            C[(size_t)m * TH + n] = acc[i][j] + bias[n];
        }
    }
}

// ---------------------------------------------------------------------------
// Kernel 2: GRU step — register-streaming, barrier-free main loop, f32x2.
// 512 threads = 4 K-groups x 128. grid = (64 j-tiles, 2 n-halves).
// Thread: 4 n x 1 j x 3 gates; accs are f32x2 packed ALONG K (contiguous
// LDG.128 of h and w gives aligned register pairs for free).
// W streams L2->regs (each element read by 1 thread/block); h rows broadcast
// within the warp (L1). NO smem staging, NO barriers until the reduction.
// Mask factored out of the GEMM: (h*m)@W == m*(h@W) exactly since m in {0,1}.
// ---------------------------------------------------------------------------
#define KGN 4
#define KPER 256   // 1024 / KGN

#define FMA2(d, a, b, c) \
    asm("fma.rn.f32x2 %0, %1, %2, %3;" : "=l"(d) : "l"(a), "l"(b), "l"(c))

__device__ __forceinline__ float sigmoidf_(float x) {
    return 1.f / (1.f + expf(-x));
}
__device__ __forceinline__ float f2lo(uint64_t v) {
    return __uint_as_float((uint32_t)v);
}
__device__ __forceinline__ float f2hi(uint64_t v) {
    return __uint_as_float((uint32_t)(v >> 32));
}

__global__ __launch_bounds__(512) void gru_step_kernel(
    const float* __restrict__ gi_t,   // [64, 3072]
    const float* __restrict__ mask_t, // [64]
    const float* __restrict__ w_hh,   // [3072, 1024]
    const float* __restrict__ b_hh,   // [3072]
    const float* __restrict__ h_prev, // [64, 1024]
    float* __restrict__ h_out)        // [64, 1024]
{
    __shared__ float red[3 * 128 * 12];   // partials from K-groups 1..3
    __shared__ float msk[32];

    const int tid = threadIdx.x;
    const int kg  = tid >> 7;        // 0..3
    const int t   = tid & 127;
    const int tn  = t >> 4;          // 0..7 -> 4 n each
    const int tj  = t & 15;
    const int j0  = blockIdx.x * 16;
    const int n_base = blockIdx.y * 32;
    const int kbase = kg * KPER;

    if (tid < 32) msk[tid] = mask_t[n_base + tid];

    const float* ph0 = h_prev + (size_t)(n_base + tn * 4 + 0) * HH + kbase;
    const float* ph1 = h_prev + (size_t)(n_base + tn * 4 + 1) * HH + kbase;
    const float* ph2 = h_prev + (size_t)(n_base + tn * 4 + 2) * HH + kbase;
    const float* ph3 = h_prev + (size_t)(n_base + tn * 4 + 3) * HH + kbase;
    const int j = j0 + tj;
    const float* pwr = w_hh + (size_t)(0 * HH + j) * HH + kbase;
    const float* pwz = w_hh + (size_t)(1 * HH + j) * HH + kbase;
    const float* pwn = w_hh + (size_t)(2 * HH + j) * HH + kbase;

    // 12 packed accumulators: [n-sub 0..3][gate r,z,n], pairs along k
    uint64_t a0r = 0, a0z = 0, a0n = 0;
    uint64_t a1r = 0, a1z = 0, a1n = 0;
    uint64_t a2r = 0, a2z = 0, a2n = 0;
    uint64_t a3r = 0, a3z = 0, a3n = 0;

#pragma unroll 4
    for (int k = 0; k < KPER; k += 4) {
        ulonglong2 h0 = *(const ulonglong2*)(ph0 + k);
        ulonglong2 h1 = *(const ulonglong2*)(ph1 + k);
        ulonglong2 h2 = *(const ulonglong2*)(ph2 + k);
        ulonglong2 h3 = *(const ulonglong2*)(ph3 + k);
        ulonglong2 wr = *(const ulonglong2*)(pwr + k);
        ulonglong2 wz = *(const ulonglong2*)(pwz + k);
        ulonglong2 wn = *(const ulonglong2*)(pwn + k);

        FMA2(a0r, h0.x, wr.x, a0r); FMA2(a0r, h0.y, wr.y, a0r);
        FMA2(a0z, h0.x, wz.x, a0z); FMA2(a0z, h0.y, wz.y, a0z);
        FMA2(a0n, h0.x, wn.x, a0n); FMA2(a0n, h0.y, wn.y, a0n);
        FMA2(a1r, h1.x, wr.x, a1r); FMA2(a1r, h1.y, wr.y, a1r);
        FMA2(a1z, h1.x, wz.x, a1z); FMA2(a1z, h1.y, wz.y, a1z);
        FMA2(a1n, h1.x, wn.x, a1n); FMA2(a1n, h1.y, wn.y, a1n);
        FMA2(a2r, h2.x, wr.x, a2r); FMA2(a2r, h2.y, wr.y, a2r);
        FMA2(a2z, h2.x, wz.x, a2z); FMA2(a2z, h2.y, wz.y, a2z);
        FMA2(a2n, h2.x, wn.x, a2n); FMA2(a2n, h2.y, wn.y, a2n);
        FMA2(a3r, h3.x, wr.x, a3r); FMA2(a3r, h3.y, wr.y, a3r);
        FMA2(a3z, h3.x, wz.x, a3z); FMA2(a3z, h3.y, wz.y, a3z);
        FMA2(a3n, h3.x, wn.x, a3n); FMA2(a3n, h3.y, wn.y, a3n);
    }

    // collapse k-pairs
    float dr[4], dz[4], dn[4];
    dr[0] = f2lo(a0r) + f2hi(a0r); dz[0] = f2lo(a0z) + f2hi(a0z); dn[0] = f2lo(a0n) + f2hi(a0n);
    dr[1] = f2lo(a1r) + f2hi(a1r); dz[1] = f2lo(a1z) + f2hi(a1z); dn[1] = f2lo(a1n) + f2hi(a1n);
    dr[2] = f2lo(a2r) + f2hi(a2r); dz[2] = f2lo(a2z) + f2hi(a2z); dn[2] = f2lo(a2n) + f2hi(a2n);
    dr[3] = f2lo(a3r) + f2hi(a3r); dz[3] = f2lo(a3z) + f2hi(a3z); dn[3] = f2lo(a3n) + f2hi(a3n);

    if (kg > 0) {
        float* r = red + (size_t)(kg - 1) * (128 * 12) + t * 12;
#pragma unroll
        for (int i = 0; i < 4; i++) {
            r[i]     = dr[i];
            r[4 + i] = dz[i];
            r[8 + i] = dn[i];
        }
    }
    __syncthreads();   // orders red AND msk

    if (kg == 0) {
        const float br = b_hh[j];
        const float bz = b_hh[HH + j];
        const float bn = b_hh[2 * HH + j];
        const float* r0 = red + t * 12;
        const float* r1 = red + 128 * 12 + t * 12;
        const float* r2 = red + 2 * 128 * 12 + t * 12;
#pragma unroll
        for (int i = 0; i < 4; i++) {
            int nl = tn * 4 + i;
            int nglob = n_base + nl;
            float m = msk[nl];
            float ghr = m * (dr[i] + r0[i]     + r1[i]     + r2[i])     + br;
            float ghz = m * (dz[i] + r0[4 + i] + r1[4 + i] + r2[4 + i]) + bz;
            float ghn = m * (dn[i] + r0[8 + i] + r1[8 + i] + r2[8 + i]) + bn;
            const float* girow = gi_t + (size_t)nglob * TH;
            float gir = girow[j];
            float giz = girow[HH + j];
            float gin = girow[2 * HH + j];
            float hm  = h_prev[(size_t)nglob * HH + j] * m;
            float r  = sigmoidf_(gir + ghr);
            float z  = sigmoidf_(giz + ghz);
            float nn = tanhf(gin + r * ghn);
            h_out[(size_t)nglob * HH + j] = (1.f - z) * nn + z * hm;
        }
    }
}

// ---------------------------------------------------------------------------
extern "C" void kernel_launch(void* const* d_in, const int* in_sizes, int n_in,
                              void* d_out, int out_size)
{
    const float* x    = (const float*)d_in[0];
    const float* hx   = (const float*)d_in[1];
    const float* mask = (const float*)d_in[2];
    const float* w_ih = (const float*)d_in[3];
    const float* w_hh = (const float*)d_in[4];
    const float* b_ih = (const float*)d_in[5];
    const float* b_hh = (const float*)d_in[6];
    float* out = (float*)d_out;

    float* gi = nullptr;
    cudaGetSymbolAddress((void**)&gi, g_gi);

    // Phase 1: bulk input projection
    dim3 gg(TH / 128, (TT * NB) / 128);   // (24, 256)
    gi_gemm_kernel<<<gg, 256>>>(x, w_ih, b_ih, gi);

    // Phase 2: sequential scan
    dim3 sg(HH / 16, 2);                  // 128 blocks
    for (int tm = 0; tm < TT; tm++) {
        const float* hp = (tm == 0) ? hx : (out + (size_t)(tm - 1) * NB * HH);
        gru_step_kernel<<<sg, 512>>>(
            gi + (size_t)tm * NB * TH,
            mask + tm * NB,
            w_hh, b_hh,
            hp,
            out + (size_t)tm * NB * HH);
    }

    // h_final == out[T-1]
    cudaMemcpyAsync(out + (size_t)TT * NB * HH,
                    out + (size_t)(TT - 1) * NB * HH,
                    (size_t)NB * HH * sizeof(float),
                    cudaMemcpyDeviceToDevice, 0);
}